// round 13
// baseline (speedup 1.0000x reference)
#include <cuda_runtime.h>
#include <cstdint>

#define BB 8
#define FF 2048
#define LL 1024
#define THRESH 0.81f
#define BN_EPS 1e-5f

// scratch (device globals per allocation rules)
__device__ float g_h[BB * FF];     // raw pooled prelu means (k1 output)
__device__ float g_hbn[BB * FF];   // BN'd h
__device__ float g_dinv[BB * FF];  // rsqrt(degree)
__device__ unsigned g_c23[BB];     // k23 arrivals per batch (self-resetting)
__device__ unsigned g_c4[BB];      // k4 arrivals per batch (self-resetting)
__device__ volatile unsigned g_flag[BB];  // batch-ready flags (self-resetting)

// ---------------- k1: prelu + mean over L (warp-per-row, R4-exact) ----------
// grid = BB*FF/8 = 2048 blocks, 256 threads = 8 warps. MLP=8 per lane.
__global__ void k1_rowmean(const float* __restrict__ x,
                           const float* __restrict__ w1p) {
    const float w1 = w1p[0];
    const int warp = threadIdx.x >> 5, lane = threadIdx.x & 31;
    const int row = blockIdx.x * 8 + warp;
    const float4* xr = (const float4*)(x + (size_t)row * LL);

    float4 v[8];
    #pragma unroll
    for (int j = 0; j < 8; j++) v[j] = xr[lane + 32 * j];

    float s = 0.f;
    #pragma unroll
    for (int j = 0; j < 8; j++) {
        s += (v[j].x >= 0.f) ? v[j].x : w1 * v[j].x;
        s += (v[j].y >= 0.f) ? v[j].y : w1 * v[j].y;
        s += (v[j].z >= 0.f) ? v[j].z : w1 * v[j].z;
        s += (v[j].w >= 0.f) ? v[j].w : w1 * v[j].w;
    }
    #pragma unroll
    for (int o = 16; o; o >>= 1) s += __shfl_down_sync(0xffffffffu, s, o);
    if (lane == 0) g_h[row] = s * (1.0f / LL);
}

// ---------------- k234: fused (BN+degree) producers + output consumers ------
// grid = 256 + 4096 = 4352 blocks, 512 threads, 32KB static smem.
// Blocks 0..255: k23 role (32 per batch). Blocks 256..: k4 role (512 per batch,
// 4 rows each), gated per-batch by g_flag[b]. Wave-1 residency (>=296 CTAs)
// guarantees all producer blocks run immediately -> no deadlock.
#define NPROD 256
__global__ void __launch_bounds__(512)
k234(const float* __restrict__ bw, const float* __restrict__ bb,
     float* __restrict__ out) {
    __shared__ __align__(128) float smem[4 * FF];  // 32 KB
    const int tid = threadIdx.x;
    const int bid = blockIdx.x;

    if (bid < NPROD) {
        // ================= k23 role: BN (redundant) + degree =================
        const int b = bid >> 5;          // 0..7
        const int sl = bid & 31;         // 64-row slice
        float* sh = smem;                // first 8 KB

        #pragma unroll
        for (int c = 0; c < 4; c++) {
            const int f = tid + c * 512;
            float v[BB];
            float mu = 0.f;
            #pragma unroll
            for (int q = 0; q < BB; q++) { v[q] = g_h[q * FF + f]; mu += v[q]; }
            mu *= (1.0f / BB);
            float var = 0.f;
            #pragma unroll
            for (int q = 0; q < BB; q++) { float d = v[q] - mu; var += d * d; }
            var *= (1.0f / BB);
            const float hv = (v[b] - mu) * rsqrtf(var + BN_EPS) * bw[f] + bb[f];
            sh[f] = hv;
            if ((f >> 6) == sl) g_hbn[b * FF + f] = hv;
        }
        __syncthreads();

        // degree count: warp w -> 4 rows
        const int warp = tid >> 5, lane = tid & 31;
        const int nbase = sl * 64 + warp * 4;
        float hn[4], cnt[4] = {0.f, 0.f, 0.f, 0.f};
        #pragma unroll
        for (int r = 0; r < 4; r++) hn[r] = sh[nbase + r];

        const float4* s4 = (const float4*)sh;
        #pragma unroll 4
        for (int i = lane; i < FF / 4; i += 32) {
            float4 v = s4[i];
            #pragma unroll
            for (int r = 0; r < 4; r++) {
                // exact FMUL-then-compare semantics as reference sim > THRESH
                cnt[r] += (hn[r] * v.x > THRESH) ? 1.f : 0.f;
                cnt[r] += (hn[r] * v.y > THRESH) ? 1.f : 0.f;
                cnt[r] += (hn[r] * v.z > THRESH) ? 1.f : 0.f;
                cnt[r] += (hn[r] * v.w > THRESH) ? 1.f : 0.f;
            }
        }
        #pragma unroll
        for (int r = 0; r < 4; r++) {
            #pragma unroll
            for (int o = 16; o; o >>= 1)
                cnt[r] += __shfl_down_sync(0xffffffffu, cnt[r], o);
        }
        if (lane == 0) {
            #pragma unroll
            for (int r = 0; r < 4; r++)
                g_dinv[b * FF + nbase + r] = rsqrtf(cnt[r] + 1.0f); // +1 identity
        }

        // publish: all threads fence, then last block of this batch raises flag
        __threadfence();
        __syncthreads();
        if (tid == 0) {
            unsigned old = atomicAdd(&g_c23[b], 1u);
            if (old == 31u) {
                g_c23[b] = 0u;            // reset for next replay
                __threadfence();
                g_flag[b] = 1u;           // release batch b consumers
            }
        }
    } else {
        // ================= k4 role: expand 4 output rows =====================
        const int bid4 = bid - NPROD;
        const int b = bid4 >> 9;          // 512 blocks per batch
        const int n0 = (bid4 & 511) * 4;

        // gate on producer flag for this batch
        if (tid == 0) {
            while (g_flag[b] == 0u) __nanosleep(128);
        }
        __syncthreads();
        __threadfence();   // acquire

        const float* __restrict__ hb = g_hbn + b * FF;
        const float* __restrict__ db = g_dinv + b * FF;

        // one float4 m-column group per thread (512 threads cover FF/4)
        float4 h4 = ((const float4*)hb)[tid];
        float4 d4 = ((const float4*)db)[tid];
        float hm[4] = {h4.x, h4.y, h4.z, h4.w};
        float dm[4] = {d4.x, d4.y, d4.z, d4.w};

        float4* t4 = (float4*)smem;
        #pragma unroll
        for (int nn = 0; nn < 4; nn++) {
            const int n = n0 + nn;
            const float hn = hb[n];       // uniform -> broadcast, L1 hit
            const float dn = db[n];
            const float diag = dn * dn;
            float4 r;
            float* rp = &r.x;
            #pragma unroll
            for (int k = 0; k < 4; k++) {
                float v = (hn * hm[k] > THRESH) ? dn * dm[k] : 0.f;
                if (tid * 4 + k == n) v += diag;
                rp[k] = v;
            }
            t4[nn * (FF / 4) + tid] = r;
        }
        __syncthreads();

        if (tid == 0) {
            asm volatile("fence.proxy.async.shared::cta;" ::: "memory");
            uint32_t saddr;
            asm("{ .reg .u64 t; cvta.to.shared.u64 t, %1; cvt.u32.u64 %0, t; }"
                : "=r"(saddr) : "l"(smem));
            float* gdst = out + (size_t)b * FF * FF + (size_t)n0 * FF;
            const unsigned bytes = 4 * FF * 4;  // 32768
            asm volatile(
                "cp.async.bulk.global.shared::cta.bulk_group [%0], [%1], %2;"
                :: "l"(gdst), "r"(saddr), "r"(bytes) : "memory");
            asm volatile("cp.async.bulk.commit_group;" ::: "memory");
            asm volatile("cp.async.bulk.wait_group.read 0;" ::: "memory");
            // last consumer of batch b resets the flag for next graph replay
            unsigned old = atomicAdd(&g_c4[b], 1u);
            if (old == 511u) {
                g_c4[b] = 0u;
                g_flag[b] = 0u;
            }
        }
    }
}

extern "C" void kernel_launch(void* const* d_in, const int* in_sizes, int n_in,
                              void* d_out, int out_size) {
    const float* x   = (const float*)d_in[0];
    const float* w1  = (const float*)d_in[1];
    // d_in[2] = prelu2_w: unused — A_hat is provably nonnegative, PReLU is identity
    const float* bnw = (const float*)d_in[3];
    const float* bnb = (const float*)d_in[4];
    float* out = (float*)d_out;

    k1_rowmean<<<BB * FF / 8, 256>>>(x, w1);
    k234<<<NPROD + BB * (FF / 4), 512>>>(bnw, bnb, out);
}